// round 1
// baseline (speedup 1.0000x reference)
#include <cuda_runtime.h>

#define D_MODEL 256
#define NHEAD   8
#define DH      32
#define SEQ     2048
#define NB      4
#define EPSV    1e-9f
#define SCALE   0.17677669529663687f   /* 1/sqrt(32) */

typedef unsigned long long ull;

/* ---------------- scratch (no allocations allowed) ---------------- */
__device__ float g_q [NB*SEQ*D_MODEL];
__device__ float g_k [SEQ*D_MODEL];
__device__ float g_v [NB*SEQ*D_MODEL];
__device__ float g_rs[NB*SEQ];
__device__ float g_o [NB*SEQ*D_MODEL];

/* ---------------- f32x2 packed-math helpers ---------------- */
__device__ __forceinline__ ull pk2(float x, float y) {
    ull r; asm("mov.b64 %0, {%1,%2};" : "=l"(r) : "f"(x), "f"(y)); return r;
}
__device__ __forceinline__ ull fma2(ull a, ull b, ull c) {
    ull d; asm("fma.rn.f32x2 %0, %1, %2, %3;" : "=l"(d) : "l"(a), "l"(b), "l"(c)); return d;
}
__device__ __forceinline__ float2 upk(ull v) {
    float x, y; asm("mov.b64 {%0,%1}, %2;" : "=f"(x), "=f"(y) : "l"(v));
    float2 r; r.x = x; r.y = y; return r;
}

/* =================================================================
 * GEMM: C[M,256] = A[M,256] @ W[256,256]^T + bias
 * BM=64 BN=64 BK=32, 256 threads, thread tile 4m x 4n (f32x2 pairs over n)
 * ================================================================= */
__global__ void __launch_bounds__(256) gemm256(
    const float* __restrict__ A, const float* __restrict__ W,
    const float* __restrict__ bias, float* __restrict__ C)
{
    __shared__ float sA[64 * 36];   /* [m][k], stride 36 */
    __shared__ float sB[32 * 64];   /* [k][n] transposed W tile */

    const int t    = threadIdx.x;
    const int row0 = blockIdx.x * 64;
    const int col0 = blockIdx.y * 64;
    const int tx = t & 15, ty = t >> 4;
    const int m0 = ty * 4, n0 = tx * 4;

    ull acc[4][2];
#pragma unroll
    for (int i = 0; i < 4; i++) { acc[i][0] = 0ull; acc[i][1] = 0ull; }

    const int fm = t >> 2, fk = (t & 3) * 8;     /* A-fill mapping  */
    const int fn = t & 63, fkc = (t >> 6) * 8;   /* W-fill mapping  */

    for (int kt = 0; kt < 8; kt++) {
        /* fill A tile */
        const float4* pa = (const float4*)(A + (size_t)(row0 + fm) * 256 + kt * 32 + fk);
        float4 a0 = pa[0], a1 = pa[1];
        *(float4*)&sA[fm * 36 + fk]     = a0;
        *(float4*)&sA[fm * 36 + fk + 4] = a1;
        /* fill W tile (transposed) */
        const float4* pw = (const float4*)(W + (size_t)(col0 + fn) * 256 + kt * 32 + fkc);
        float4 w0 = pw[0], w1 = pw[1];
        sB[(fkc + 0) * 64 + fn] = w0.x; sB[(fkc + 1) * 64 + fn] = w0.y;
        sB[(fkc + 2) * 64 + fn] = w0.z; sB[(fkc + 3) * 64 + fn] = w0.w;
        sB[(fkc + 4) * 64 + fn] = w1.x; sB[(fkc + 5) * 64 + fn] = w1.y;
        sB[(fkc + 6) * 64 + fn] = w1.z; sB[(fkc + 7) * 64 + fn] = w1.w;
        __syncthreads();

#pragma unroll
        for (int k4 = 0; k4 < 8; k4++) {
            float4 av[4];
#pragma unroll
            for (int i = 0; i < 4; i++)
                av[i] = *(const float4*)&sA[(m0 + i) * 36 + k4 * 4];
#pragma unroll
            for (int c = 0; c < 4; c++) {
                ulonglong2 bb = *(const ulonglong2*)&sB[(k4 * 4 + c) * 64 + n0];
#pragma unroll
                for (int i = 0; i < 4; i++) {
                    float a = (c == 0) ? av[i].x : (c == 1) ? av[i].y : (c == 2) ? av[i].z : av[i].w;
                    ull ad = pk2(a, a);
                    acc[i][0] = fma2(ad, bb.x, acc[i][0]);
                    acc[i][1] = fma2(ad, bb.y, acc[i][1]);
                }
            }
        }
        __syncthreads();
    }

    float4 bi = *(const float4*)&bias[col0 + n0];
#pragma unroll
    for (int i = 0; i < 4; i++) {
        float2 r0 = upk(acc[i][0]), r1 = upk(acc[i][1]);
        float4 o; o.x = r0.x + bi.x; o.y = r0.y + bi.y; o.z = r1.x + bi.z; o.w = r1.y + bi.w;
        *(float4*)&C[(size_t)(row0 + m0 + i) * 256 + col0 + n0] = o;
    }
}

/* =================================================================
 * Row-wise reciprocal of sum of inverse distances: g_rs[row] = 1/sum(1/(d+eps))
 * ================================================================= */
__global__ void __launch_bounds__(256) rsumk(
    const float* __restrict__ dist, float* __restrict__ out)
{
    const int row = blockIdx.x;
    const float4* p = (const float4*)(dist + (size_t)row * 2048);
    const int t = threadIdx.x;

    float s = 0.f;
#pragma unroll
    for (int it = 0; it < 2; it++) {
        float4 x = p[t + it * 256];
        s += 1.0f / (x.x + EPSV) + 1.0f / (x.y + EPSV)
           + 1.0f / (x.z + EPSV) + 1.0f / (x.w + EPSV);
    }
#pragma unroll
    for (int off = 16; off > 0; off >>= 1)
        s += __shfl_xor_sync(0xffffffffu, s, off);

    __shared__ float red[8];
    if ((t & 31) == 0) red[t >> 5] = s;
    __syncthreads();
    if (t == 0) {
        float tot = 0.f;
#pragma unroll
        for (int w = 0; w < 8; w++) tot += red[w];
        out[row] = 1.0f / tot;
    }
}

/* =================================================================
 * Fused attention. One block = (batch b, 32 q-rows, all 8 heads).
 * warp = head. Thread tile: 4 q-rows x 8 s (scores) / 4 q x 8 d (output).
 * Single-pass exp (scores*dw bounded, no max needed).
 * ================================================================= */
#define ATTN_SMEM_FLOATS (8192 + 9216 + 8192 + 1056 + 32)

__global__ void __launch_bounds__(256, 2) attnk(
    const float* __restrict__ Q, const float* __restrict__ K,
    const float* __restrict__ V, const float* __restrict__ DIST,
    const float* __restrict__ RS, float* __restrict__ O)
{
    extern __shared__ float sm[];
    float* sQt = sm;            /* [256 dims][32 q]            */
    float* sKt = sm + 8192;     /* [256 dims][32 s], stride 36 */
    float* sV  = sm + 17408;    /* [32 s][256 dims]            */
    float* sW  = sm + 25600;    /* [32 q][32 s], stride 33     */
    float* sRs = sm + 26656;    /* [32 q]                      */

    const int b  = blockIdx.y;
    const int qb = blockIdx.x * 32;
    const int t  = threadIdx.x;
    const int lane = t & 31, h = t >> 5;
    const int uq = lane & 7, us = lane >> 3;
    const int q0 = uq * 4, s0 = us * 8, d0 = us * 8;
    const int kb = h * 32;

    /* ---- fill Q transposed (scale folded in) + rs ---- */
    {
        const int qq = t & 31, dc = (t >> 5) * 32;
        const float* src = Q + (size_t)(b * SEQ + qb + qq) * 256 + dc;
#pragma unroll
        for (int c = 0; c < 8; c++) {
            float4 x = *(const float4*)(src + c * 4);
            int d = dc + c * 4;
            sQt[(d + 0) * 32 + qq] = x.x * SCALE;
            sQt[(d + 1) * 32 + qq] = x.y * SCALE;
            sQt[(d + 2) * 32 + qq] = x.z * SCALE;
            sQt[(d + 3) * 32 + qq] = x.w * SCALE;
        }
        if (t < 32) sRs[t] = RS[b * SEQ + qb + t];
    }
    __syncthreads();

    ull oacc[4][4];
#pragma unroll
    for (int i = 0; i < 4; i++)
#pragma unroll
        for (int j = 0; j < 4; j++) oacc[i][j] = 0ull;
    float rden[4] = {0.f, 0.f, 0.f, 0.f};

    for (int st = 0; st < 64; st++) {
        const int sb = st * 32;

        /* ---- fill K transposed ---- */
        {
            const int ss = t & 31, dc = (t >> 5) * 32;
            const float* src = K + (size_t)(sb + ss) * 256 + dc;
#pragma unroll
            for (int c = 0; c < 8; c++) {
                float4 x = *(const float4*)(src + c * 4);
                int d = dc + c * 4;
                sKt[(d + 0) * 36 + ss] = x.x;
                sKt[(d + 1) * 36 + ss] = x.y;
                sKt[(d + 2) * 36 + ss] = x.z;
                sKt[(d + 3) * 36 + ss] = x.w;
            }
        }
        /* ---- fill V row-major ---- */
        {
            const int ss = t >> 3, dc = (t & 7) * 32;
            const float4* src = (const float4*)(V + (size_t)(b * SEQ + sb + ss) * 256 + dc);
            float4* dst = (float4*)(sV + ss * 256 + dc);
#pragma unroll
            for (int c = 0; c < 8; c++) dst[c] = src[c];
        }
        /* ---- fill distance weights w = rs / (d + eps) ---- */
        {
            const int qq = t >> 3, sc = (t & 7) * 4;
            float4 dd = *(const float4*)(DIST + (size_t)(b * SEQ + qb + qq) * 2048 + sb + sc);
            float rs = sRs[qq];
            sW[qq * 33 + sc + 0] = rs / (dd.x + EPSV);
            sW[qq * 33 + sc + 1] = rs / (dd.y + EPSV);
            sW[qq * 33 + sc + 2] = rs / (dd.z + EPSV);
            sW[qq * 33 + sc + 3] = rs / (dd.w + EPSV);
        }
        __syncthreads();

        /* ---- scores: 32x32 per head, f32x2 over s-pairs ---- */
        ull racc[4][4];
#pragma unroll
        for (int i = 0; i < 4; i++)
#pragma unroll
            for (int j = 0; j < 4; j++) racc[i][j] = 0ull;

#pragma unroll 8
        for (int c = 0; c < 32; c++) {
            float4 qv = *(const float4*)&sQt[(kb + c) * 32 + q0];
            ulonglong2 b0 = *(const ulonglong2*)&sKt[(kb + c) * 36 + s0];
            ulonglong2 b1 = *(const ulonglong2*)&sKt[(kb + c) * 36 + s0 + 4];
            ull a;
            a = pk2(qv.x, qv.x);
            racc[0][0] = fma2(a, b0.x, racc[0][0]); racc[0][1] = fma2(a, b0.y, racc[0][1]);
            racc[0][2] = fma2(a, b1.x, racc[0][2]); racc[0][3] = fma2(a, b1.y, racc[0][3]);
            a = pk2(qv.y, qv.y);
            racc[1][0] = fma2(a, b0.x, racc[1][0]); racc[1][1] = fma2(a, b0.y, racc[1][1]);
            racc[1][2] = fma2(a, b1.x, racc[1][2]); racc[1][3] = fma2(a, b1.y, racc[1][3]);
            a = pk2(qv.z, qv.z);
            racc[2][0] = fma2(a, b0.x, racc[2][0]); racc[2][1] = fma2(a, b0.y, racc[2][1]);
            racc[2][2] = fma2(a, b1.x, racc[2][2]); racc[2][3] = fma2(a, b1.y, racc[2][3]);
            a = pk2(qv.w, qv.w);
            racc[3][0] = fma2(a, b0.x, racc[3][0]); racc[3][1] = fma2(a, b0.y, racc[3][1]);
            racc[3][2] = fma2(a, b1.x, racc[3][2]); racc[3][3] = fma2(a, b1.y, racc[3][3]);
        }

        /* ---- weight * exp, denominator ---- */
        float p[4][8];
#pragma unroll
        for (int i = 0; i < 4; i++) {
            const float* wr = &sW[(q0 + i) * 33 + s0];
            float2 x0 = upk(racc[i][0]), x1 = upk(racc[i][1]);
            float2 x2 = upk(racc[i][2]), x3 = upk(racc[i][3]);
            p[i][0] = __expf(x0.x * wr[0]); p[i][1] = __expf(x0.y * wr[1]);
            p[i][2] = __expf(x1.x * wr[2]); p[i][3] = __expf(x1.y * wr[3]);
            p[i][4] = __expf(x2.x * wr[4]); p[i][5] = __expf(x2.y * wr[5]);
            p[i][6] = __expf(x3.x * wr[6]); p[i][7] = __expf(x3.y * wr[7]);
            float dl = ((p[i][0] + p[i][1]) + (p[i][2] + p[i][3]))
                     + ((p[i][4] + p[i][5]) + (p[i][6] + p[i][7]));
            dl += __shfl_xor_sync(0xffffffffu, dl, 8);
            dl += __shfl_xor_sync(0xffffffffu, dl, 16);
            rden[i] += dl;
        }

        /* ---- P @ V via warp shuffle broadcast of P ---- */
        for (int sg = 0; sg < 4; sg++) {
            const int srcl = sg * 8 + uq;
#pragma unroll
            for (int j = 0; j < 8; j++) {
                const float* vr = &sV[(sg * 8 + j) * 256 + kb + d0];
                ulonglong2 v0 = *(const ulonglong2*)vr;
                ulonglong2 v1 = *(const ulonglong2*)(vr + 4);
#pragma unroll
                for (int i = 0; i < 4; i++) {
                    float pi = __shfl_sync(0xffffffffu, p[i][j], srcl);
                    ull a = pk2(pi, pi);
                    oacc[i][0] = fma2(a, v0.x, oacc[i][0]);
                    oacc[i][1] = fma2(a, v0.y, oacc[i][1]);
                    oacc[i][2] = fma2(a, v1.x, oacc[i][2]);
                    oacc[i][3] = fma2(a, v1.y, oacc[i][3]);
                }
            }
        }
        __syncthreads();
    }

    /* ---- normalize + write ---- */
#pragma unroll
    for (int i = 0; i < 4; i++) {
        float inv = 1.0f / rden[i];
        float2 o0 = upk(oacc[i][0]), o1 = upk(oacc[i][1]);
        float2 o2 = upk(oacc[i][2]), o3 = upk(oacc[i][3]);
        float4 w0, w1;
        w0.x = o0.x * inv; w0.y = o0.y * inv; w0.z = o1.x * inv; w0.w = o1.y * inv;
        w1.x = o2.x * inv; w1.y = o2.y * inv; w1.z = o3.x * inv; w1.w = o3.y * inv;
        float* dst = O + (size_t)(b * SEQ + qb + q0 + i) * 256 + kb + d0;
        *(float4*)dst       = w0;
        *(float4*)(dst + 4) = w1;
    }
}

/* ================================================================= */
extern "C" void kernel_launch(void* const* d_in, const int* in_sizes, int n_in,
                              void* d_out, int out_size)
{
    const float* query  = (const float*)d_in[0];
    const float* values = (const float*)d_in[1];
    const float* dist   = (const float*)d_in[2];
    const float* Wq     = (const float*)d_in[3];
    const float* Wqb    = (const float*)d_in[4];
    const float* Wk     = (const float*)d_in[5];
    const float* Wkb    = (const float*)d_in[6];
    const float* Wv     = (const float*)d_in[7];
    const float* Wvb    = (const float*)d_in[8];
    const float* fcw    = (const float*)d_in[9];
    const float* fcb    = (const float*)d_in[10];
    const float* keys   = (const float*)d_in[11];
    float* out = (float*)d_out;

    void *pq, *pk, *pv, *prs, *po;
    cudaGetSymbolAddress(&pq,  g_q);
    cudaGetSymbolAddress(&pk,  g_k);
    cudaGetSymbolAddress(&pv,  g_v);
    cudaGetSymbolAddress(&prs, g_rs);
    cudaGetSymbolAddress(&po,  g_o);

    const int smem_bytes = ATTN_SMEM_FLOATS * 4;  /* 106752 */
    cudaFuncSetAttribute(attnk, cudaFuncAttributeMaxDynamicSharedMemorySize, smem_bytes);

    /* projections */
    gemm256<<<dim3(128, 4), 256>>>(query,  Wq, Wqb, (float*)pq);
    gemm256<<<dim3(32,  4), 256>>>(keys,   Wk, Wkb, (float*)pk);
    gemm256<<<dim3(128, 4), 256>>>(values, Wv, Wvb, (float*)pv);
    /* distance-weight denominators */
    rsumk<<<NB * SEQ, 256>>>(dist, (float*)prs);
    /* fused attention */
    attnk<<<dim3(64, 4), 256, smem_bytes>>>((const float*)pq, (const float*)pk,
                                            (const float*)pv, dist,
                                            (const float*)prs, (float*)po);
    /* output projection */
    gemm256<<<dim3(128, 4), 256>>>((const float*)po, fcw, fcb, out);
}